// round 4
// baseline (speedup 1.0000x reference)
#include <cuda_runtime.h>
#include <math.h>

#define H 64
#define MAX_N 65536
#define CAP 64
#define MAX_OVF 65536

// Static scratch. All counters are self-cleaning: zero at module load, and
// each call re-zeroes what it consumed, so every call (and graph replay)
// starts from zeroed state.
__device__ float g_f[MAX_N * H];        // feature * src_norm (+ zero row at n)
__device__ int   g_ebuf[MAX_N * CAP];   // dst-binned src indices
__device__ int   g_cnt[MAX_N];          // in-degree / bin cursor
__device__ int   g_degout[MAX_N];       // out-degree
__device__ int2  g_ovf[MAX_OVF];        // overflow (dst, src) pairs
__device__ int   g_ovf_n;               // live overflow counter (reset by k_scale)
__device__ int   g_ovf_n2;              // snapshot for k_gather

// One pass over edges: out-degree histogram + dst-binning.
__global__ void k_bin(const int* __restrict__ src, const int* __restrict__ dst, int e) {
    int i = blockIdx.x * blockDim.x + threadIdx.x;
    if (i < e) {
        int s = src[i];
        int d = dst[i];
        atomicAdd(&g_degout[s], 1);
        int pos = atomicAdd(&g_cnt[d], 1);
        if (pos < CAP) {
            g_ebuf[d * CAP + pos] = s;
        } else {
            int k = atomicAdd(&g_ovf_n, 1);
            if (k < MAX_OVF) g_ovf[k] = make_int2(d, s);
        }
    }
}

// Prescale: g_f = feat * rsqrt(max(degout,1)). 256 threads = 4 whole nodes
// per block, so read-before-zero of g_degout is safe via __syncthreads.
// Also snapshots + resets the overflow counter.
__global__ void k_scale(const float* __restrict__ feat, int n) {
    int i = blockIdx.x * blockDim.x + threadIdx.x;
    int node = i >> 6;
    float d = 0.f;
    bool ok = node < n;
    if (ok) d = (float)g_degout[node];
    __syncthreads();
    if (ok) {
        g_f[i] = feat[i] * rsqrtf(fmaxf(d, 1.f));
        if ((i & 63) == 0) g_degout[node] = 0;
    }
    if (i == 0) { g_ovf_n2 = g_ovf_n; g_ovf_n = 0; }
}

// Fused gather-SpMM + epilogue. TWO nodes per warp (one per 16-lane half,
// float4 per lane). Fully uniform control flow: outer bound is the max
// degree of the two halves; invalid bin slots read the zero row at index n.
__global__ void k_gather(const float* __restrict__ feat,
                         const float* __restrict__ hw,
                         const float* __restrict__ hb,
                         const int* __restrict__ niter_p,
                         float* __restrict__ out, int n) {
    int gwarp = (blockIdx.x * blockDim.x + threadIdx.x) >> 5;
    int lane  = threadIdx.x & 31;
    int half  = lane >> 4;
    int hl    = lane & 15;
    int node  = gwarp * 2 + half;
    bool active = node < n;
    int nodec = active ? node : 0;
    unsigned hmask = half ? 0xFFFF0000u : 0x0000FFFFu;

    int deg  = active ? g_cnt[nodec] : 0;   // true in-degree
    int degb = min(deg, CAP);
    float dn = rsqrtf(fmaxf((float)deg, 1.f));

    // Uniform outer bound across the warp's two halves.
    int degm = max(degb, __shfl_xor_sync(0xffffffffu, degb, 16));

    const float4* F4 = (const float4*)g_f;
    float4 a0 = make_float4(0.f, 0.f, 0.f, 0.f);
    float4 a1 = make_float4(0.f, 0.f, 0.f, 0.f);

    const int* bin = g_ebuf + nodec * CAP;
    for (int base = 0; base < degm; base += 16) {
        int idx = base + hl;
        int s_l = (idx < degb) ? bin[idx] : n;   // zero row for padding
        int m = min(16, degm - base);            // uniform across warp
        int k = 0;
        for (; k + 2 <= m; k += 2) {
            int s0 = __shfl_sync(0xffffffffu, s_l, k, 16);
            int s1 = __shfl_sync(0xffffffffu, s_l, k + 1, 16);
            float4 v0 = F4[(size_t)s0 * 16 + hl];
            float4 v1 = F4[(size_t)s1 * 16 + hl];
            a0.x += v0.x; a0.y += v0.y; a0.z += v0.z; a0.w += v0.w;
            a1.x += v1.x; a1.y += v1.y; a1.z += v1.z; a1.w += v1.w;
        }
        if (k < m) {
            int s0 = __shfl_sync(0xffffffffu, s_l, k, 16);
            float4 v0 = F4[(size_t)s0 * 16 + hl];
            a0.x += v0.x; a0.y += v0.y; a0.z += v0.z; a0.w += v0.w;
        }
    }
    float4 acc;
    acc.x = a0.x + a1.x; acc.y = a0.y + a1.y;
    acc.z = a0.z + a1.z; acc.w = a0.w + a1.w;

    // Overflow edges (empty in practice; correct if not)
    if (deg > CAP) {
        int novf = min(g_ovf_n2, MAX_OVF);
        for (int i = 0; i < novf; i++) {
            int2 pr = g_ovf[i];
            if (pr.x == node) {
                float4 v = F4[(size_t)pr.y * 16 + hl];
                acc.x += v.x; acc.y += v.y; acc.z += v.z; acc.w += v.w;
            }
        }
    }

    // Reset bin cursor for the next call (own value already read).
    if (active && hl == 0) g_cnt[node] = 0;

    // prop = acc * dn; halting head
    float4 p;
    p.x = acc.x * dn; p.y = acc.y * dn; p.z = acc.z * dn; p.w = acc.w * dn;
    float4 w = ((const float4*)hw)[hl];
    float dot = w.x * p.x + w.y * p.y + w.z * p.z + w.w * p.w;
    #pragma unroll
    for (int o = 8; o > 0; o >>= 1)
        dot += __shfl_xor_sync(hmask, dot, o, 16);
    float z = dot + hb[0];
    float h = 1.f / (1.f + expf(-z));

    int niter = niter_p ? *niter_p : 10;
    float niter_f = (float)niter;

    // Exact emulation of the halting recurrence (prop/h loop-invariant, so
    // only iteration 0's p blends in `feature`; every later active iteration
    // contributes exactly `prop`). Verified bit-compatible R1-R3.
    float steps = 1.f, sum_h = 0.f;
    bool cont = true;
    float pfirst = 1.f;
    int U = 0;
    for (int t = 0; t < niter; ++t) {
        bool prob = (sum_h + h < 0.99f) && cont;
        if (cont) U++;
        float probf = prob ? 1.f : 0.f;
        steps += probf;
        sum_h += probf * h;
        bool condition = prob && (steps < niter_f);
        float pp = condition ? sum_h : 1.f - sum_h;
        if (t == 0) pfirst = pp;
        cont = cont && prob;
    }

    float cprop = pfirst + (float)(U - 1);
    float cfeat = 1.f - pfirst;

    if (active) {
        const float4* FT4 = (const float4*)feat;
        float4 f = FT4[(size_t)node * 16 + hl];
        float inv_steps = 1.f / steps;
        float4 r;
        r.x = (p.x * cprop + f.x * cfeat) * inv_steps;
        r.y = (p.y * cprop + f.y * cfeat) * inv_steps;
        r.z = (p.z * cprop + f.z * cfeat) * inv_steps;
        r.w = (p.w * cprop + f.w * cfeat) * inv_steps;
        ((float4*)out)[(size_t)node * 16 + hl] = r;
        if (hl == 0) {
            out[(size_t)n * H + node] = steps;            // steps
            out[(size_t)n * H + n + node] = 1.f - sum_h;  // remainder
        }
    }
}

extern "C" void kernel_launch(void* const* d_in, const int* in_sizes, int n_in,
                              void* d_out, int out_size) {
    const float* feat = (const float*)d_in[0];
    const int*   src  = (const int*)d_in[1];
    const int*   dst  = (const int*)d_in[2];
    const float* hw   = (const float*)d_in[3];
    const float* hb   = (const float*)d_in[4];
    const int*   nit  = (n_in >= 6) ? (const int*)d_in[5] : nullptr;

    int n = in_sizes[0] / H;
    int e = in_sizes[1];
    float* out = (float*)d_out;

    k_bin<<<(e + 255) / 256, 256>>>(src, dst, e);
    k_scale<<<(n * H + 255) / 256, 256>>>(feat, n);
    {
        long long threads = (long long)((n + 1) / 2) * 32;
        int blocks = (int)((threads + 255) / 256);
        k_gather<<<blocks, 256>>>(feat, hw, hb, nit, out, n);
    }
}